// round 2
// baseline (speedup 1.0000x reference)
#include <cuda_runtime.h>
#include <cstdint>

#define BB 8
#define SS 2048
#define NN 512
#define DD 1024
#define WW 32
#define MASK_FILL (-1000.0f)

// Scratch for precomputed global attention logits (B*S floats = 64 KB).
__device__ float g_logits[BB * SS];

// ---------------------------------------------------------------------------
// Kernel 1: logits[b*S+s] = dot(seq[b,s,:], att_w) + att_b
// One warp per row. 8 warps/block -> grid = B*S/8 = 2048 blocks.
// ---------------------------------------------------------------------------
__global__ void __launch_bounds__(256) logits_kernel(
    const float* __restrict__ seq,
    const float* __restrict__ att_w,
    const float* __restrict__ att_b)
{
    int gwarp = (blockIdx.x * blockDim.x + threadIdx.x) >> 5;   // row id
    int lane  = threadIdx.x & 31;
    if (gwarp >= BB * SS) return;

    const float4* row = reinterpret_cast<const float4*>(seq) + (size_t)gwarp * (DD / 4);
    const float4* wv  = reinterpret_cast<const float4*>(att_w);

    float acc = 0.0f;
#pragma unroll
    for (int i = 0; i < DD / 4 / 32; i++) {   // 8 iterations
        float4 a = row[lane + 32 * i];
        float4 b = wv [lane + 32 * i];
        acc += a.x * b.x + a.y * b.y + a.z * b.z + a.w * b.w;
    }
#pragma unroll
    for (int o = 16; o; o >>= 1)
        acc += __shfl_xor_sync(0xffffffffu, acc, o);

    if (lane == 0)
        g_logits[gwarp] = acc + att_b[0];
}

// ---------------------------------------------------------------------------
// Kernel 2: one block per (b, n).
//   warp 0: gather 32 logits, masked softmax (mask underflows to exact 0)
//   all 256 threads: out[b,n,d] = sum_w attn[w] * seq[b, idx[w], d]
// Masked positions (w > width) have attn == 0 exactly (expf(-1000-m) == 0 in
// fp32, identical to the fp32 jnp softmax), so we skip them -> halves traffic.
// ---------------------------------------------------------------------------
__global__ void __launch_bounds__(256) span_kernel(
    const float* __restrict__ seq,
    const int*   __restrict__ spans,
    float*       __restrict__ out)
{
    const int bn = blockIdx.x;          // 0 .. B*N-1
    const int b  = bn >> 9;             // N = 512

    __shared__ float s_attn[WW];
    __shared__ int   s_idx[WW];
    __shared__ int   s_cnt;

    const int tid = threadIdx.x;

    if (tid < 32) {
        const int start = spans[bn * 2 + 0];
        const int end   = spans[bn * 2 + 1];   // inclusive
        const int width = end - start;
        const int w   = tid;
        const int raw = end - w;
        const bool ok = (w <= width) && (raw >= 0);
        const int idx = raw > 0 ? raw : 0;

        float lg = ok ? g_logits[b * SS + idx] : MASK_FILL;

        // warp softmax over 32 lanes
        float m = lg;
#pragma unroll
        for (int o = 16; o; o >>= 1)
            m = fmaxf(m, __shfl_xor_sync(0xffffffffu, m, o));
        float e = __expf(lg - m);
        float sum = e;
#pragma unroll
        for (int o = 16; o; o >>= 1)
            sum += __shfl_xor_sync(0xffffffffu, sum, o);

        s_attn[w] = e / sum;
        s_idx[w]  = idx;
        if (w == 0) {
            int c = width < (WW - 1) ? width : (WW - 1);
            s_cnt = c + 1;                 // number of rows with attn != 0
        }
    }
    __syncthreads();

    const int cnt = s_cnt;
    const float4* base = reinterpret_cast<const float4*>(seq) + (size_t)b * SS * (DD / 4);

    float4 acc = make_float4(0.f, 0.f, 0.f, 0.f);

    int w = 0;
    // unroll-by-4 main loop for MLP
    for (; w + 4 <= cnt; w += 4) {
        float a0 = s_attn[w + 0]; int i0 = s_idx[w + 0];
        float a1 = s_attn[w + 1]; int i1 = s_idx[w + 1];
        float a2 = s_attn[w + 2]; int i2 = s_idx[w + 2];
        float a3 = s_attn[w + 3]; int i3 = s_idx[w + 3];
        float4 v0 = base[i0 * (DD / 4) + tid];
        float4 v1 = base[i1 * (DD / 4) + tid];
        float4 v2 = base[i2 * (DD / 4) + tid];
        float4 v3 = base[i3 * (DD / 4) + tid];
        acc.x += a0 * v0.x; acc.y += a0 * v0.y; acc.z += a0 * v0.z; acc.w += a0 * v0.w;
        acc.x += a1 * v1.x; acc.y += a1 * v1.y; acc.z += a1 * v1.z; acc.w += a1 * v1.w;
        acc.x += a2 * v2.x; acc.y += a2 * v2.y; acc.z += a2 * v2.z; acc.w += a2 * v2.w;
        acc.x += a3 * v3.x; acc.y += a3 * v3.y; acc.z += a3 * v3.z; acc.w += a3 * v3.w;
    }
    for (; w < cnt; w++) {
        float a = s_attn[w];
        float4 v = base[s_idx[w] * (DD / 4) + tid];
        acc.x += a * v.x; acc.y += a * v.y; acc.z += a * v.z; acc.w += a * v.w;
    }

    reinterpret_cast<float4*>(out)[(size_t)bn * (DD / 4) + tid] = acc;
}

// ---------------------------------------------------------------------------
// Launch
// inputs: [0] sequence_tensor f32 (B,S,D)  [1] span_indices i32 (B,N,2)
//         [2] att_w f32 (D,1)              [3] att_b f32 (1)
// output: f32 (B,N,D)
// ---------------------------------------------------------------------------
extern "C" void kernel_launch(void* const* d_in, const int* in_sizes, int n_in,
                              void* d_out, int out_size)
{
    const float* seq   = (const float*)d_in[0];
    const int*   spans = (const int*)  d_in[1];
    const float* att_w = (const float*)d_in[2];
    const float* att_b = (const float*)d_in[3];
    float*       out   = (float*)d_out;

    (void)in_sizes; (void)n_in; (void)out_size;

    logits_kernel<<<(BB * SS) / 8, 256>>>(seq, att_w, att_b);
    span_kernel<<<BB * NN, 256>>>(seq, spans, out);
}